// round 13
// baseline (speedup 1.0000x reference)
#include <cuda_runtime.h>

#define NN    8192
#define NBINS 8192               // bin = fkey >> 19 (sign + exp + 4 mantissa bits)
#define GRID  128
#define BT    512
#define NBAR  7                  // barriers per run

#define TILE   256
#define NTILES (NN / TILE)       // 32
#define NWORDS (NN / 32)         // 256 words per tile bitmap

// ---- global scratch (allocation-free) ----
__device__ unsigned int       g_hist[2][NBINS];
__device__ unsigned int       g_base[2][NBINS];
__device__ unsigned int       g_cursor[2][NBINS];
__device__ unsigned int       g_binlo[2][NN];      // low-32 keys grouped by bin
__device__ int                g_r[NN];             // rank of X[p]
__device__ int                g_B[NN];             // argsort(X_hat): B[rank] = index
__device__ int                g_tau[NN];
__device__ unsigned int       g_bitmapflat[NTILES * NWORDS];
__device__ unsigned long long g_pb[NTILES * NWORDS]; // (prefix_popc<<32) | bitmap word
__device__ unsigned int       g_count;
__device__ unsigned int       g_done;
__device__ unsigned int       g_barcnt  = 0;       // monotone, never reset
__device__ unsigned int       g_barbase = 0;       // per-run base, updated by last block

// Monotone uint32 mapping of float (total order == float < for finite values)
__device__ __forceinline__ unsigned int fkey(float f) {
    unsigned int u = __float_as_uint(f);
    return (u & 0x80000000u) ? ~u : (u | 0x80000000u);
}
// 45-bit key = (fkey << 13) | idx; bin = fkey >> 19. Within a bin, order of the
// full key == order of lo = (fkey << 13) | idx (exact stable-argsort tie-break).

// Monotone-counter grid barrier. All GRID blocks call it in identical order.
// Correct under replay: counter never resets; target is relative to per-run base.
__device__ __forceinline__ void gridbar(unsigned int target) {
    __syncthreads();
    if (threadIdx.x == 0) {
        __threadfence();
        atomicAdd(&g_barcnt, 1u);
        while ((int)(*(volatile unsigned int*)&g_barcnt - target) < 0)
            __nanosleep(20);
        __threadfence();
    }
    __syncthreads();
}

__global__ void __launch_bounds__(BT, 1)
kendall_kernel(const float* __restrict__ X, const float* __restrict__ Xh,
               float* __restrict__ out) {
    __shared__ unsigned int s_warp[32];
    __shared__ int s_tau[TILE];
    __shared__ unsigned int s_sum;

    const int b = blockIdx.x;
    const int t = threadIdx.x;
    const unsigned int base = g_barbase;   // stable during the run

    // ---- P0: zero hist + bitmap + counters ----
    {
        const int idx = b * 192 + t;       // 24576 words / 128 blocks = 192
        if (t < 192) {
            if (idx < 2 * NBINS) ((unsigned int*)g_hist)[idx] = 0;
            else                 g_bitmapflat[idx - 2 * NBINS] = 0;
        }
        if (b == 0 && t == 0) { g_count = 0; g_done = 0; }
    }
    gridbar(base + 1 * GRID);

    // ---- P1: histogram (flat element space: 16384 / 128 blocks = 128 each) ----
    if (t < 128) {
        const int e = b * 128 + t;
        const int arr = e >> 13, p = e & (NN - 1);
        const float f = arr ? Xh[p] : X[p];
        atomicAdd(&g_hist[arr][fkey(f) >> 19], 1u);
    }
    gridbar(base + 2 * GRID);

    // ---- P2: exclusive scan of each histogram (blocks 0 and 1) ----
    if (b < 2) {
        const int arr = b;
        const int w = t >> 5, l = t & 31;
        unsigned int h[16], tsum = 0;
        #pragma unroll
        for (int k = 0; k < 16; k++) { h[k] = g_hist[arr][t * 16 + k]; tsum += h[k]; }
        unsigned int incl = tsum;
        #pragma unroll
        for (int off = 1; off < 32; off <<= 1) {
            const unsigned int u = __shfl_up_sync(0xffffffffu, incl, off);
            if (l >= off) incl += u;
        }
        if (l == 31) s_warp[w] = incl;
        __syncthreads();
        if (t < 16) {
            const unsigned int v = s_warp[t];
            unsigned int wi = v;
            #pragma unroll
            for (int off = 1; off < 16; off <<= 1) {
                const unsigned int u = __shfl_up_sync(0xffffu, wi, off);
                if (t >= off) wi += u;
            }
            s_warp[t] = wi - v;            // exclusive warp base
        }
        __syncthreads();
        unsigned int run = s_warp[w] + (incl - tsum);
        #pragma unroll
        for (int k = 0; k < 16; k++) {
            g_base[arr][t * 16 + k]   = run;
            g_cursor[arr][t * 16 + k] = run;
            run += h[k];
        }
    }
    gridbar(base + 3 * GRID);

    // ---- P3: scatter low-keys into bin-grouped order ----
    if (t < 128) {
        const int e = b * 128 + t;
        const int arr = e >> 13, p = e & (NN - 1);
        const float f = arr ? Xh[p] : X[p];
        const unsigned int fk = fkey(f);
        const unsigned int slot = atomicAdd(&g_cursor[arr][fk >> 19], 1u);
        g_binlo[arr][slot] = (fk << 13) | (unsigned int)p;
    }
    gridbar(base + 4 * GRID);

    // ---- P4: exact rank = base[bin] + #{same-bin lo-keys < mine}; 4 lanes/element ----
    {
        const int e = b * 128 + (t >> 2);
        const int part = t & 3;
        const int arr = e >> 13, p = e & (NN - 1);
        const float f = arr ? Xh[p] : X[p];
        const unsigned int fk = fkey(f);
        const unsigned int lo = (fk << 13) | (unsigned int)p;
        const unsigned int bn = fk >> 19;
        const unsigned int st = g_base[arr][bn];
        const unsigned int m  = g_hist[arr][bn];
        unsigned int cnt = 0;
        for (unsigned int j = st + part; j < st + m; j += 4)
            cnt += (__ldg(&g_binlo[arr][j]) < lo) ? 1u : 0u;
        cnt += __shfl_xor_sync(0xffffffffu, cnt, 1);
        cnt += __shfl_xor_sync(0xffffffffu, cnt, 2);
        if (part == 0) {
            const unsigned int r = st + cnt;
            if (arr) g_B[r] = p;
            else     g_r[p] = (int)r;
        }
    }
    gridbar(base + 5 * GRID);

    // ---- P5: tau = B o r; set value bits per position-tile (8192 atomicOr total) ----
    if (t < 64) {
        const int i = b * 64 + t;
        const int v = g_B[g_r[i]];
        g_tau[i] = v;
        atomicOr(&g_bitmapflat[(i >> 8) * NWORDS + (v >> 5)], 1u << (v & 31));
    }
    gridbar(base + 6 * GRID);

    // ---- P6: per-tile exclusive prefix popcounts, packed with the word (blocks 0..31) ----
    if (b < NTILES) {
        unsigned int word = 0, c = 0, incl = 0;
        const int w = t >> 5, l = t & 31;
        if (t < NWORDS) {
            word = g_bitmapflat[b * NWORDS + t];
            c = __popc(word);
            incl = c;
            #pragma unroll
            for (int off = 1; off < 32; off <<= 1) {
                const unsigned int u = __shfl_up_sync(0xffffffffu, incl, off);
                if (l >= off) incl += u;
            }
            if (l == 31) s_warp[w] = incl;
        }
        __syncthreads();
        if (t < 8) {
            const unsigned int v = s_warp[t];
            unsigned int wi = v;
            #pragma unroll
            for (int off = 1; off < 8; off <<= 1) {
                const unsigned int u = __shfl_up_sync(0xffu, wi, off);
                if (t >= off) wi += u;
            }
            s_warp[t] = wi - v;
        }
        __syncthreads();
        if (t < NWORDS) {
            const unsigned int pref = s_warp[w] + (incl - c);  // exclusive
            g_pb[b * NWORDS + t] = ((unsigned long long)pref << 32) | word;
        }
    }
    gridbar(base + 7 * GRID);

    // ---- P7: inversion count. 64 rows/block, 8 lanes/row. ----
    {
        const int I = b >> 2;                 // tile of this block's rows
        if (t < TILE) s_tau[t] = g_tau[I * TILE + t];
        if (t == 0) s_sum = 0;
        __syncthreads();

        const int row = t >> 3, part = t & 7;
        const int i  = b * 64 + row;
        const int il = i & (TILE - 1);
        const int v  = s_tau[il];
        unsigned int cnt = 0;

        // within-tile: j in (il, 256)
        for (int j = il + 1 + part; j < TILE; j += 8)
            cnt += (s_tau[j] < v) ? 1u : 0u;

        // cross-tile: all positions in tiles J > I; count values < v via packed pref|word
        {
            const unsigned int w = (unsigned int)v >> 5;
            const unsigned int mask = (1u << (v & 31)) - 1u;
            for (int J = I + 1 + part; J < NTILES; J += 8) {
                const unsigned long long pb = __ldg(&g_pb[J * NWORDS + w]);
                cnt += (unsigned int)(pb >> 32) + __popc((unsigned int)pb & mask);
            }
        }
        cnt += __shfl_xor_sync(0xffffffffu, cnt, 1);
        cnt += __shfl_xor_sync(0xffffffffu, cnt, 2);
        cnt += __shfl_xor_sync(0xffffffffu, cnt, 4);
        if (part == 0) atomicAdd(&s_sum, cnt);
        __syncthreads();

        if (t == 0) {
            atomicAdd(&g_count, s_sum);
            __threadfence();
            const unsigned int d = atomicAdd(&g_done, 1u);
            if (d == GRID - 1) {
                const unsigned int tot = atomicAdd(&g_count, 0u);
                out[0] = (float)(2.0 * (double)tot / ((double)NN * (double)(NN - 1)));
                g_barbase = base + NBAR * GRID;   // advance barrier base for next replay
            }
        }
    }
}

extern "C" void kernel_launch(void* const* d_in, const int* in_sizes, int n_in,
                              void* d_out, int out_size) {
    const float* X  = (const float*)d_in[0];
    const float* Xh = (const float*)d_in[1];
    float* out = (float*)d_out;
    kendall_kernel<<<GRID, BT>>>(X, Xh, out);
}

// round 15
// speedup vs baseline: 2.0766x; 2.0766x over previous
#include <cuda_runtime.h>

#define NN 8192

// ---- K1 (rank) ----
#define NBINS 8192                 // bin = fkey >> 19 (sign + exp + 4 mantissa bits)
#define K1_T 1024
#define K1_SLICES 16               // blocks per array; each ranks NN/K1_SLICES elements
#define K1_EPB (NN / K1_SLICES)    // 512

// ---- tiles / bitmaps ----
#define TILE 256
#define NTILES (NN / TILE)         // 32
#define NWORDS (NN / 32)           // 256 bitmap words per tile

// ---- K3 (count) ----
#define K3_BLOCKS 128              // 64 rows per block
#define K3_T 512                   // 8 lanes per row

__device__ int                g_r[NN];     // rank of X[p]
__device__ int                g_B[NN];     // argsort(X_hat): B[rank] = index
__device__ int                g_tau[NN];
__device__ unsigned long long g_pb[NTILES * NWORDS]; // (excl. prefix popc << 32) | word
__device__ unsigned int       g_count;
__device__ unsigned int       g_done;

// Monotone uint32 mapping of float (total order == float < for finite values)
__device__ __forceinline__ unsigned int fkey(float f) {
    unsigned int u = __float_as_uint(f);
    return (u & 0x80000000u) ? ~u : (u | 0x80000000u);
}
// Full 45-bit key = (fkey << 13) | idx. bin = fkey >> 19. Within one bin the high
// bits are identical, so ordering == ordering of lo = (fkey << 13) | idx
// (exact stable-argsort index tie-break).

// K1: exact ranks via redundant per-block smem histogram + scan + bin-grouped compare.
// grid (K1_SLICES, 2 arrays), block K1_T. Dyn smem: hist | cursor | binlo | warpsum.
__global__ void rank_kernel(const float* __restrict__ X, const float* __restrict__ Xh) {
    extern __shared__ unsigned int s1[];
    unsigned int* hist    = s1;                 // [NBINS] counts (kept intact)
    unsigned int* cursor  = s1 + NBINS;         // [NBINS] excl. prefix -> bin end after scatter
    unsigned int* binlo   = s1 + 2 * NBINS;     // [NN] low-32 keys grouped by bin
    unsigned int* warpsum = s1 + 3 * NBINS;     // [32]

    const int arr = blockIdx.y;
    const float* __restrict__ src = arr ? Xh : X;
    const int t = threadIdx.x;

    // zero histogram
    #pragma unroll
    for (int k = 0; k < NBINS / K1_T; k++) hist[t + k * K1_T] = 0;
    __syncthreads();

    // load ALL elements (8/thread), histogram; keep keys in registers
    unsigned int lo[8], bin[8];
    #pragma unroll
    for (int k = 0; k < 8; k++) {
        const int e = t + k * K1_T;
        const unsigned int fk = fkey(src[e]);
        lo[k]  = (fk << 13) | (unsigned int)e;
        bin[k] = fk >> 19;
        atomicAdd(&hist[bin[k]], 1u);
    }
    __syncthreads();

    // exclusive scan of hist -> cursor (thread t owns bins [8t, 8t+8))
    unsigned int h[8], tsum = 0;
    #pragma unroll
    for (int k = 0; k < 8; k++) { h[k] = hist[t * 8 + k]; tsum += h[k]; }
    unsigned int incl = tsum;
    #pragma unroll
    for (int off = 1; off < 32; off <<= 1) {
        const unsigned int u = __shfl_up_sync(0xffffffffu, incl, off);
        if ((t & 31) >= off) incl += u;
    }
    if ((t & 31) == 31) warpsum[t >> 5] = incl;
    __syncthreads();
    if (t < 32) {
        const unsigned int w = warpsum[t];
        unsigned int wi = w;
        #pragma unroll
        for (int off = 1; off < 32; off <<= 1) {
            const unsigned int u = __shfl_up_sync(0xffffffffu, wi, off);
            if (t >= off) wi += u;
        }
        warpsum[t] = wi - w;   // exclusive warp base
    }
    __syncthreads();
    unsigned int run = warpsum[t >> 5] + (incl - tsum);
    #pragma unroll
    for (int k = 0; k < 8; k++) { cursor[t * 8 + k] = run; run += h[k]; }
    __syncthreads();

    // scatter low-keys into bin-grouped order (in-bin order irrelevant)
    #pragma unroll
    for (int k = 0; k < 8; k++) {
        const unsigned int slot = atomicAdd(&cursor[bin[k]], 1u);
        binlo[slot] = lo[k];
    }
    __syncthreads();

    // exact rank for this block's slice: 2 lanes per element
    {
        const int e = blockIdx.x * K1_EPB + (t >> 1);
        const int part = t & 1;
        const unsigned int fk = fkey(src[e]);      // L1-hot reload
        const unsigned int mylo = (fk << 13) | (unsigned int)e;
        const unsigned int b = fk >> 19;
        const unsigned int end = cursor[b];        // base + count
        const unsigned int start = end - hist[b];
        unsigned int cnt = 0;
        for (unsigned int j = start + part; j < end; j += 2)
            cnt += (binlo[j] < mylo) ? 1u : 0u;
        cnt += __shfl_xor_sync(0xffffffffu, cnt, 1);
        if (part == 0) {
            const unsigned int r = start + cnt;
            if (arr) g_B[r] = e;
            else     g_r[e] = (int)r;
        }
    }
}

// K2: build tau and ONE tile's bitmap + exclusive prefix popcounts per block.
// grid NTILES, block TILE.
__global__ void build_kernel() {
    __shared__ unsigned int bm[NWORDS];
    __shared__ unsigned int s_warp[8];
    const int J = blockIdx.x, t = threadIdx.x;

    bm[t] = 0;
    __syncthreads();

    const int i = J * TILE + t;
    const int v = g_B[g_r[i]];
    g_tau[i] = v;
    atomicOr(&bm[v >> 5], 1u << (v & 31));
    __syncthreads();

    // exclusive prefix popcount across the 256 words
    const unsigned int word = bm[t];
    const unsigned int c = __popc(word);
    unsigned int incl = c;
    const int w = t >> 5, l = t & 31;
    #pragma unroll
    for (int off = 1; off < 32; off <<= 1) {
        const unsigned int u = __shfl_up_sync(0xffffffffu, incl, off);
        if (l >= off) incl += u;
    }
    if (l == 31) s_warp[w] = incl;
    __syncthreads();
    if (t < 8) {
        const unsigned int v8 = s_warp[t];
        unsigned int wi = v8;
        #pragma unroll
        for (int off = 1; off < 8; off <<= 1) {
            const unsigned int u = __shfl_up_sync(0xffu, wi, off);
            if (t >= off) wi += u;
        }
        s_warp[t] = wi - v8;   // exclusive warp base
    }
    __syncthreads();
    const unsigned int pref = s_warp[w] + (incl - c);
    g_pb[J * NWORDS + t] = ((unsigned long long)pref << 32) | word;

    if (J == 0 && t == 0) { g_count = 0; g_done = 0; }
}

// K3: inversion count. 64 rows/block, 8 lanes/row; finalize in last-done block.
__global__ void __launch_bounds__(K3_T, 2)
count_kernel(float* __restrict__ out) {
    __shared__ int s_tau[TILE];
    __shared__ unsigned int s_sum;
    const int b = blockIdx.x, t = threadIdx.x;
    const int I = b >> 2;                     // this block's position-tile

    if (t < TILE) s_tau[t] = g_tau[I * TILE + t];
    if (t == 0) s_sum = 0;
    __syncthreads();

    const int row = t >> 3, part = t & 7;
    const int i  = b * 64 + row;
    const int il = i & (TILE - 1);
    const int v  = s_tau[il];
    unsigned int cnt = 0;

    // within-tile: j in (il, 256), 8-lane strided
    for (int j = il + 1 + part; j < TILE; j += 8)
        cnt += (s_tau[j] < v) ? 1u : 0u;

    // cross-tile: tiles J > I, values < v via packed (pref|word) lookups
    {
        const unsigned int w = (unsigned int)v >> 5;
        const unsigned int mask = (1u << (v & 31)) - 1u;
        for (int J = I + 1 + part; J < NTILES; J += 8) {
            const unsigned long long pb = __ldg(&g_pb[J * NWORDS + w]);
            cnt += (unsigned int)(pb >> 32) + __popc((unsigned int)pb & mask);
        }
    }

    // warp sum of raw partials (each lane is a distinct partial) -> one atomic/warp
    cnt = __reduce_add_sync(0xffffffffu, cnt);
    if ((t & 31) == 0) atomicAdd(&s_sum, cnt);
    __syncthreads();

    if (t == 0) {
        atomicAdd(&g_count, s_sum);
        __threadfence();
        const unsigned int d = atomicAdd(&g_done, 1u);
        if (d == K3_BLOCKS - 1) {
            const unsigned int tot = atomicAdd(&g_count, 0u);
            out[0] = (float)(2.0 * (double)tot / ((double)NN * (double)(NN - 1)));
        }
    }
}

extern "C" void kernel_launch(void* const* d_in, const int* in_sizes, int n_in,
                              void* d_out, int out_size) {
    const float* X  = (const float*)d_in[0];
    const float* Xh = (const float*)d_in[1];
    float* out = (float*)d_out;

    const int smem1 = (3 * NBINS + 32) * (int)sizeof(unsigned int);  // 98,432 B
    cudaFuncSetAttribute(rank_kernel, cudaFuncAttributeMaxDynamicSharedMemorySize, smem1);

    dim3 g1(K1_SLICES, 2);
    rank_kernel<<<g1, K1_T, smem1>>>(X, Xh);
    build_kernel<<<NTILES, TILE>>>();
    count_kernel<<<K3_BLOCKS, K3_T>>>(out);
}